// round 14
// baseline (speedup 1.0000x reference)
#include <cuda_runtime.h>

#define H 1024
#define B 8
#define T 4096
#define NROWS (B * T)

#define GRID      296              // 148 SMs x 2 blocks — all co-resident
#define NWARPS    (GRID * 8)       // 2368 warps, ~14 rows each
#define VW_BLOCKS 128              // blocks 0..127: 8 warps x 1 row = 1024 v-rows

__device__ float g_v[B * H];
__device__ int   g_cnt;            // writer blocks done (self-resetting)
__device__ int   g_passed;         // blocks past spin (self-resetting)

__device__ __forceinline__ int ld_acquire(const int* p) {
    int v;
    asm volatile("ld.global.acquire.gpu.b32 %0, [%1];" : "=r"(v) : "l"(p) : "memory");
    return v;
}

__device__ __forceinline__ void load_row(float4 (&x)[8],
                                         const float* __restrict__ states,
                                         int row, int lane)
{
    const float4* s4 = reinterpret_cast<const float4*>(states + (size_t)row * H);
#pragma unroll
    for (int k = 0; k < 8; k++) x[k] = s4[lane + 32 * k];
}

__device__ __forceinline__ void dot_store(const float4 (&x)[8],
                                          int row, int lane, float bb,
                                          float* __restrict__ out)
{
    const float4* v4 = reinterpret_cast<const float4*>(g_v + ((row >> 12) << 10));
    float acc0 = 0.0f, acc1 = 0.0f;
#pragma unroll
    for (int k = 0; k < 8; k += 2) {
        const float4 w0 = __ldg(v4 + lane + 32 * k);
        const float4 w1 = __ldg(v4 + lane + 32 * (k + 1));
        acc0 += x[k].x * w0.x + x[k].y * w0.y + x[k].z * w0.z + x[k].w * w0.w;
        acc1 += x[k+1].x * w1.x + x[k+1].y * w1.y + x[k+1].z * w1.z + x[k+1].w * w1.w;
    }
    float acc = acc0 + acc1;
#pragma unroll
    for (int o = 16; o; o >>= 1)
        acc += __shfl_xor_sync(0xFFFFFFFFu, acc, o);
    if (lane == 0) out[row] = acc + bb;
}

__global__ void __launch_bounds__(256, 2) fused_kernel(
    const float* __restrict__ states,  // (B, T, H)
    const float* __restrict__ ctx,     // (B, H)
    const float* __restrict__ W,       // (H, H)
    const float* __restrict__ bias,    // (1,)
    float* __restrict__ out)           // (B*T,)
{
    const int tid  = threadIdx.x;
    const int lane = tid & 31;
    const int warp = tid >> 5;
    const int wg   = blockIdx.x * 8 + warp;
    const bool writer = blockIdx.x < VW_BLOCKS;

    float4 xa[8], xb[8];

    if (writer) {
        // ── v-phase: ONE W row per warp (wg = 0..1023) ──
        const int row = wg;
        const float4* wr = reinterpret_cast<const float4*>(W + (size_t)row * H);
        float4 w[8];
#pragma unroll
        for (int k = 0; k < 8; k++) w[k] = wr[lane + 32 * k];   // front-batched DRAM

        float acc[B];
#pragma unroll
        for (int b = 0; b < B; b++) {
            const float4* c4 = reinterpret_cast<const float4*>(ctx + b * H);
            float a = 0.0f;
#pragma unroll
            for (int k = 0; k < 8; k++) {
                const float4 c = __ldg(c4 + lane + 32 * k);     // L1-hot (shared by 8 warps)
                a += w[k].x * c.x + w[k].y * c.y + w[k].z * c.z + w[k].w * c.w;
            }
            acc[b] = a;
        }
#pragma unroll
        for (int b = 0; b < B; b++) {
#pragma unroll
            for (int o = 16; o; o >>= 1)
                acc[b] += __shfl_xor_sync(0xFFFFFFFFu, acc[b], o);
        }
        if (lane == 0) {
#pragma unroll
            for (int b = 0; b < B; b++) g_v[b * H + row] = acc[b];
        }
        __syncthreads();                  // all 8 warps' g_v writes done
        if (tid == 0) {
            __threadfence();              // publish device-wide
            atomicAdd(&g_cnt, 1);
        }
    } else {
        // Non-writers: pre-issue first states row — DRAM busy during v-phase.
        load_row(xa, states, wg, lane);
    }

    const float bb = bias[0];

    // ── spin barrier: wait for all 128 writer blocks; self-reset for replay ──
    if (tid == 0) {
        while (ld_acquire(&g_cnt) < VW_BLOCKS) __nanosleep(32);
        const int old = atomicAdd(&g_passed, 1);
        if (old == GRID - 1) {
            atomicExch(&g_cnt, 0);
            atomicExch(&g_passed, 0);
        }
    }
    __syncthreads();

    // Writers load their first row only now (no live range across v-phase).
    if (writer) load_row(xa, states, wg, lane);

    // ── engine: register ping-pong over ~14 rows per warp ──
    int ra = wg;
    int rb = ra + NWARPS;
    for (;;) {
        if (rb < NROWS) load_row(xb, states, rb, lane);   // prefetch next
        dot_store(xa, ra, lane, bb, out);                 // consume current
        if (rb >= NROWS) break;

        ra = rb + NWARPS;
        if (ra < NROWS) load_row(xa, states, ra, lane);
        dot_store(xb, rb, lane, bb, out);
        if (ra >= NROWS) break;

        rb = ra + NWARPS;
    }
}

extern "C" void kernel_launch(void* const* d_in, const int* in_sizes, int n_in,
                              void* d_out, int out_size)
{
    const float* states = (const float*)d_in[0];   // (B, T, H)
    const float* ctx    = (const float*)d_in[1];   // (B, H)
    const float* W      = (const float*)d_in[2];   // (1, H, H)
    const float* bias   = (const float*)d_in[3];   // (1,)

    fused_kernel<<<GRID, 256>>>(states, ctx, W, bias, (float*)d_out);
}